// round 16
// baseline (speedup 1.0000x reference)
#include <cuda_runtime.h>

// q,k,v,out: (B=4, S=4096, H=16, D=64) f32. Hilbert gather + inverse scatter
// cancel (attention is strictly per-position): per (b,s) two independent 8x8
// head-vs-head attentions (groups of 8 heads), inner dim 64.
//
// R9 = R7/R8 layout (warp = position; lane (g=bit4,i1=bit3,c8=bits0-2) owns
// rows {(lane>>3)*4+t} over dim chunk {4c8..}{32+4c8..}) with k and v
// streamed in QUARTERS (one owned row = 8 regs): quarter t serves exactly
// j with j&3==t (j and j+4). Shuffle/FMA totals unchanged vs R8; resident
// window halved -> target 84 regs / 6 CTAs/SM (24 warps).
#define NPOS  16384
#define SCALE 0.125f

__global__ __launch_bounds__(128, 6)
void hilbert_headattn_kernel(const float4* __restrict__ q,
                             const float4* __restrict__ k,
                             const float4* __restrict__ v,
                             float4* __restrict__ out)
{
    const int lane = threadIdx.x & 31;
    const int pos  = blockIdx.x * 4 + (threadIdx.x >> 5);
    const int c8   = lane & 7;
    // float4 index of (owned row r = (lane>>3)*4 + t, half h): tb + t*16 + h*8
    const int tb   = pos * 256 + ((lane >> 3) << 6) + c8;

    // ---- q rows in registers, SCALE folded ----
    float qr[32];
#pragma unroll
    for (int t = 0; t < 4; t++)
#pragma unroll
        for (int h = 0; h < 2; h++) {
            const float4 a = q[tb + t * 16 + h * 8];
            qr[t*8+4*h]   = a.x * SCALE;
            qr[t*8+4*h+1] = a.y * SCALE;
            qr[t*8+4*h+2] = a.z * SCALE;
            qr[t*8+4*h+3] = a.w * SCALE;
        }

    float s[4][8];

    // ---- k streamed in quarters: quarter qt (owned row qt) serves j=qt, qt+4 ----
#pragma unroll
    for (int qt = 0; qt < 4; qt++) {
        float kr[8];
#pragma unroll
        for (int h = 0; h < 2; h++) {
            const float4 b = k[tb + qt * 16 + h * 8];
            kr[4*h] = b.x; kr[4*h+1] = b.y; kr[4*h+2] = b.z; kr[4*h+3] = b.w;
        }
#pragma unroll
        for (int u = 0; u < 2; u++) {
            const int j   = qt + u * 4;
            const int src = (lane & 0x17) | ((j >> 2) << 3);   // owner of k row 8g+j
            float kb[8];
#pragma unroll
            for (int m = 0; m < 8; m++)
                kb[m] = __shfl_sync(0xffffffffu, kr[m], src);
#pragma unroll
            for (int t = 0; t < 4; t++) {
                float acc = 0.f;
#pragma unroll
                for (int m = 0; m < 8; m++)
                    acc = fmaf(qr[t*8+m], kb[m], acc);
                s[t][j] = acc;
            }
        }
    }

    // ---- allreduce partial scores over the 8 c8-lanes ----
#pragma unroll
    for (int w = 1; w < 8; w <<= 1)
#pragma unroll
        for (int t = 0; t < 4; t++)
#pragma unroll
            for (int j = 0; j < 8; j++)
                s[t][j] += __shfl_xor_sync(0xffffffffu, s[t][j], w);

    // ---- softmax over j, fully local per row ----
#pragma unroll
    for (int t = 0; t < 4; t++) {
        float mx = s[t][0];
#pragma unroll
        for (int j = 1; j < 8; j++) mx = fmaxf(mx, s[t][j]);
        float sum = 0.f;
#pragma unroll
        for (int j = 0; j < 8; j++) { s[t][j] = __expf(s[t][j] - mx); sum += s[t][j]; }
        const float inv = __frcp_rn(sum);
#pragma unroll
        for (int j = 0; j < 8; j++) s[t][j] *= inv;
    }

    // ---- AV with v streamed in quarters; o accumulates across all j ----
    float o[32];
#pragma unroll
    for (int m = 0; m < 32; m++) o[m] = 0.f;
#pragma unroll
    for (int qt = 0; qt < 4; qt++) {
        float vr[8];
#pragma unroll
        for (int h = 0; h < 2; h++) {
            const float4 b = v[tb + qt * 16 + h * 8];
            vr[4*h] = b.x; vr[4*h+1] = b.y; vr[4*h+2] = b.z; vr[4*h+3] = b.w;
        }
#pragma unroll
        for (int u = 0; u < 2; u++) {
            const int j   = qt + u * 4;
            const int src = (lane & 0x17) | ((j >> 2) << 3);
            float vb[8];
#pragma unroll
            for (int m = 0; m < 8; m++)
                vb[m] = __shfl_sync(0xffffffffu, vr[m], src);
#pragma unroll
            for (int t = 0; t < 4; t++) {
                const float a = s[t][j];
#pragma unroll
                for (int m = 0; m < 8; m++)
                    o[t*8+m] = fmaf(a, vb[m], o[t*8+m]);
            }
        }
    }

    // ---- coalesced stores ----
#pragma unroll
    for (int t = 0; t < 4; t++)
#pragma unroll
        for (int h = 0; h < 2; h++)
            out[tb + t * 16 + h * 8] =
                make_float4(o[t*8+4*h], o[t*8+4*h+1], o[t*8+4*h+2], o[t*8+4*h+3]);
}

extern "C" void kernel_launch(void* const* d_in, const int* in_sizes, int n_in,
                              void* d_out, int out_size)
{
    const float4* q = (const float4*)d_in[0];
    const float4* k = (const float4*)d_in[1];
    const float4* v = (const float4*)d_in[2];
    float4* o       = (float4*)d_out;
    // 128 threads = 4 warps = 4 positions per CTA (1 warp per position)
    hilbert_headattn_kernel<<<NPOS / 4, 128>>>(q, k, v, o);
}